// round 1
// baseline (speedup 1.0000x reference)
#include <cuda_runtime.h>

// SqueezeSeg Recurrent CRF — fused per-iteration kernel, sm_103a.
// B=16, C=4, H=64, W=512, 3x5 neighborhood (14 neighbors), 3 iterations.
//
// Math notes (verified against reference):
//  - ANG_THETA_A == BILATERAL_THETA_A == 0.9 => g_ang == g_bi => bi_ang == ang.
//  - compat = ones - eye => ang2[o] = 0.02*(sum_c ang[c] - ang[o]),
//                            bi2[o] = 0.10*(sum_c bi[c]  - bi[o]).
//  - zero padding applies to softmaxed unary (and masked unary) -> OOB u=0,m=0.

#define BATCH 16
#define NC 4
#define HH 64
#define WW 512
#define PLANE (HH*WW)

#define TH 4
#define TW 64
#define SH (TH + 2)   // halo 1 in H
#define SW (TW + 4)   // halo 2 in W
#define NTHREADS (TH * TW)

__device__ float g_scratchA[BATCH * NC * PLANE];
__device__ float g_scratchB[BATCH * NC * PLANE];

__device__ __constant__ int c_offz[14] = {0,0,0,0,0, 1,1,1,1, 2,2,2,2,2};
__device__ __constant__ int c_offa[14] = {0,1,2,3,4, 0,1,3,4, 0,1,2,3,4};

__global__ __launch_bounds__(NTHREADS)
void crf_iter_kernel(const float* __restrict__ x,
                     const float* __restrict__ bf,     // [B,14,H,W]
                     const float* __restrict__ mask,   // [B,H,W]
                     float* __restrict__ out)          // [B,4,H,W]
{
    __shared__ float s_u[NC][SH][SW];
    __shared__ float s_m[SH][SW];

    const int b  = blockIdx.z;
    const int h0 = blockIdx.y * TH;
    const int w0 = blockIdx.x * TW;
    const int tx = threadIdx.x;   // 0..63 along W
    const int ty = threadIdx.y;   // 0..3 along H
    const int tid = ty * TW + tx;

    const float* xb = x    + (size_t)b * NC * PLANE;
    const float* mb = mask + (size_t)b * PLANE;

    // Cooperative load + per-pixel softmax into smem (tile + halo).
    #pragma unroll
    for (int i = tid; i < SH * SW; i += NTHREADS) {
        const int sh = i / SW;
        const int sw = i % SW;
        const int h = h0 + sh - 1;
        const int w = w0 + sw - 2;
        float u0 = 0.f, u1 = 0.f, u2 = 0.f, u3 = 0.f, m = 0.f;
        if (h >= 0 && h < HH && w >= 0 && w < WW) {
            const int off = h * WW + w;
            const float a0 = xb[0 * PLANE + off];
            const float a1 = xb[1 * PLANE + off];
            const float a2 = xb[2 * PLANE + off];
            const float a3 = xb[3 * PLANE + off];
            const float mx = fmaxf(fmaxf(a0, a1), fmaxf(a2, a3));
            u0 = expf(a0 - mx);
            u1 = expf(a1 - mx);
            u2 = expf(a2 - mx);
            u3 = expf(a3 - mx);
            const float inv = 1.0f / (u0 + u1 + u2 + u3);
            u0 *= inv; u1 *= inv; u2 *= inv; u3 *= inv;
            m = mb[off];
        }
        s_u[0][sh][sw] = u0;
        s_u[1][sh][sw] = u1;
        s_u[2][sh][sw] = u2;
        s_u[3][sh][sw] = u3;
        s_m[sh][sw]    = m;
    }
    __syncthreads();

    const int h = h0 + ty;
    const int w = w0 + tx;
    const int off = h * WW + w;

    // Gaussian weights: d2 in {1,2,4,5}, denom 2*0.9^2 = 1.62
    const float inv_den = 1.0f / 1.62f;
    const float e1 = expf(-1.0f * inv_den);
    const float e2 = expf(-2.0f * inv_den);
    const float e4 = expf(-4.0f * inv_den);
    const float e5 = expf(-5.0f * inv_den);

    const float* bfp = bf + (size_t)b * 14 * PLANE + off;

    float ang[NC]  = {0.f, 0.f, 0.f, 0.f};
    float cond[NC] = {0.f, 0.f, 0.f, 0.f};

    #pragma unroll
    for (int k = 0; k < 14; ++k) {
        const int dz = c_offz[k];
        const int da = c_offa[k];
        const int d2 = (dz - 1) * (dz - 1) + (da - 2) * (da - 2);
        const float g = (d2 == 1) ? e1 : (d2 == 2) ? e2 : (d2 == 4) ? e4 : e5;
        const int sh = ty + dz;
        const int sw = tx + da;
        const float m   = s_m[sh][sw];
        const float bfv = bfp[k * PLANE];
        const float bm  = bfv * m;
        #pragma unroll
        for (int c = 0; c < NC; ++c) {
            const float u = s_u[c][sh][sw];
            ang[c]  = fmaf(g,  u, ang[c]);
            cond[c] = fmaf(bm, u, cond[c]);
        }
    }

    const float mc = s_m[ty + 1][tx + 2];
    float bi[NC];
    float sum_ang = 0.f, sum_bi = 0.f;
    #pragma unroll
    for (int c = 0; c < NC; ++c) {
        bi[c] = cond[c] * mc * ang[c];   // bi_ang == ang (thetas equal)
        sum_ang += ang[c];
        sum_bi  += bi[c];
    }

    float* ob = out + (size_t)b * NC * PLANE;
    #pragma unroll
    for (int c = 0; c < NC; ++c) {
        const float uc = s_u[c][ty + 1][tx + 2];
        ob[c * PLANE + off] = uc + 0.02f * (sum_ang - ang[c])
                                 + 0.10f * (sum_bi  - bi[c]);
    }
}

extern "C" void kernel_launch(void* const* d_in, const int* in_sizes, int n_in,
                              void* d_out, int out_size)
{
    const float* x    = (const float*)d_in[0];  // [16,4,64,512]
    const float* bf   = (const float*)d_in[1];  // [16,1,14,64,512]
    const float* mask = (const float*)d_in[2];  // [16,1,64,512]
    float* out = (float*)d_out;

    float* sa = nullptr;
    float* sb = nullptr;
    cudaGetSymbolAddress((void**)&sa, g_scratchA);
    cudaGetSymbolAddress((void**)&sb, g_scratchB);

    dim3 block(TW, TH, 1);                  // 256 threads
    dim3 grid(WW / TW, HH / TH, BATCH);     // 8 x 16 x 16 = 2048 blocks

    crf_iter_kernel<<<grid, block>>>(x,  bf, mask, sa);
    crf_iter_kernel<<<grid, block>>>(sa, bf, mask, sb);
    crf_iter_kernel<<<grid, block>>>(sb, bf, mask, out);
}

// round 5
// speedup vs baseline: 1.4476x; 1.4476x over previous
#include <cuda_runtime.h>

// SqueezeSeg Recurrent CRF — fused per-iteration kernel, sm_103a. Round 2.
// B=16, C=4, H=64, W=512, 3x5 neighborhood (14 neighbors), 3 iterations.
//
// Changes vs R1:
//  - smem stores softmaxed unary as float4 (all 4 classes) -> LDS.128 per
//    neighbor instead of 4x LDS.32. Mask separate scalar smem.
//  - __expf softmax (error ~5e-7, tolerance 1e-3).
//  - TH=8 x TW=64 tile, 512 threads: halo redundancy 1.59x -> 1.33x.
//
// Math notes (verified vs reference):
//  - ANG_THETA_A == BILATERAL_THETA_A => g_ang == g_bi => bi_ang == ang.
//  - compat = ones - eye => ang2[o] = 0.02*(sum_c ang[c] - ang[o]), bi2 likewise 0.10.

#define BATCH 16
#define NC 4
#define HH 64
#define WW 512
#define PLANE (HH*WW)

#define TH 8
#define TW 64
#define SH (TH + 2)   // halo 1 in H
#define SW (TW + 4)   // halo 2 in W
#define NTHREADS (TH * TW)

__device__ float g_scratchA[BATCH * NC * PLANE];
__device__ float g_scratchB[BATCH * NC * PLANE];

__global__ __launch_bounds__(NTHREADS)
void crf_iter_kernel(const float* __restrict__ x,
                     const float* __restrict__ bf,     // [B,14,H,W]
                     const float* __restrict__ mask,   // [B,H,W]
                     float* __restrict__ out)          // [B,4,H,W]
{
    __shared__ float4 s_u[SH][SW];
    __shared__ float  s_m[SH][SW];

    const int b  = blockIdx.z;
    const int h0 = blockIdx.y * TH;
    const int w0 = blockIdx.x * TW;
    const int tx = threadIdx.x;   // 0..63 along W
    const int ty = threadIdx.y;   // 0..7 along H
    const int tid = ty * TW + tx;

    const float* xb = x    + (size_t)b * NC * PLANE;
    const float* mb = mask + (size_t)b * PLANE;

    // Cooperative load + per-pixel softmax into smem (tile + halo).
    #pragma unroll
    for (int i = tid; i < SH * SW; i += NTHREADS) {
        const int sh = i / SW;
        const int sw = i % SW;
        const int h = h0 + sh - 1;
        const int w = w0 + sw - 2;
        float4 u = make_float4(0.f, 0.f, 0.f, 0.f);
        float m = 0.f;
        if (h >= 0 && h < HH && w >= 0 && w < WW) {
            const int off = h * WW + w;
            const float a0 = xb[0 * PLANE + off];
            const float a1 = xb[1 * PLANE + off];
            const float a2 = xb[2 * PLANE + off];
            const float a3 = xb[3 * PLANE + off];
            const float mx = fmaxf(fmaxf(a0, a1), fmaxf(a2, a3));
            u.x = __expf(a0 - mx);
            u.y = __expf(a1 - mx);
            u.z = __expf(a2 - mx);
            u.w = __expf(a3 - mx);
            const float inv = 1.0f / (u.x + u.y + u.z + u.w);
            u.x *= inv; u.y *= inv; u.z *= inv; u.w *= inv;
            m = mb[off];
        }
        s_u[sh][sw] = u;
        s_m[sh][sw] = m;
    }
    __syncthreads();

    const int h = h0 + ty;
    const int w = w0 + tx;
    const int off = h * WW + w;

    // Gaussian weights: d2 in {1,2,4,5}, denom 2*0.9^2 = 1.62
    const float inv_den = 1.0f / 1.62f;
    const float e1 = __expf(-1.0f * inv_den);
    const float e2 = __expf(-2.0f * inv_den);
    const float e4 = __expf(-4.0f * inv_den);
    const float e5 = __expf(-5.0f * inv_den);

    const float* bfp = bf + (size_t)b * 14 * PLANE + off;

    float4 ang  = make_float4(0.f, 0.f, 0.f, 0.f);
    float4 cond = make_float4(0.f, 0.f, 0.f, 0.f);

    // neighbor offsets (dz, da) of 3x5 kernel, center excluded
    const int offz[14] = {0,0,0,0,0, 1,1,1,1, 2,2,2,2,2};
    const int offa[14] = {0,1,2,3,4, 0,1,3,4, 0,1,2,3,4};

    #pragma unroll
    for (int k = 0; k < 14; ++k) {
        const int dz = offz[k];
        const int da = offa[k];
        const int d2 = (dz - 1) * (dz - 1) + (da - 2) * (da - 2);
        const float g = (d2 == 1) ? e1 : (d2 == 2) ? e2 : (d2 == 4) ? e4 : e5;
        const int sh = ty + dz;
        const int sw = tx + da;
        const float4 u = s_u[sh][sw];
        const float  m = s_m[sh][sw];
        const float bm = bfp[k * PLANE] * m;
        ang.x  = fmaf(g,  u.x, ang.x);
        ang.y  = fmaf(g,  u.y, ang.y);
        ang.z  = fmaf(g,  u.z, ang.z);
        ang.w  = fmaf(g,  u.w, ang.w);
        cond.x = fmaf(bm, u.x, cond.x);
        cond.y = fmaf(bm, u.y, cond.y);
        cond.z = fmaf(bm, u.z, cond.z);
        cond.w = fmaf(bm, u.w, cond.w);
    }

    const float mc = s_m[ty + 1][tx + 2];
    // bi_ang == ang (equal thetas)
    const float bix = cond.x * mc * ang.x;
    const float biy = cond.y * mc * ang.y;
    const float biz = cond.z * mc * ang.z;
    const float biw = cond.w * mc * ang.w;

    const float sum_ang = ang.x + ang.y + ang.z + ang.w;
    const float sum_bi  = bix + biy + biz + biw;

    const float4 uc = s_u[ty + 1][tx + 2];
    float* ob = out + (size_t)b * NC * PLANE;
    ob[0 * PLANE + off] = uc.x + 0.02f * (sum_ang - ang.x) + 0.10f * (sum_bi - bix);
    ob[1 * PLANE + off] = uc.y + 0.02f * (sum_ang - ang.y) + 0.10f * (sum_bi - biy);
    ob[2 * PLANE + off] = uc.z + 0.02f * (sum_ang - ang.z) + 0.10f * (sum_bi - biz);
    ob[3 * PLANE + off] = uc.w + 0.02f * (sum_ang - ang.w) + 0.10f * (sum_bi - biw);
}

extern "C" void kernel_launch(void* const* d_in, const int* in_sizes, int n_in,
                              void* d_out, int out_size)
{
    const float* x    = (const float*)d_in[0];  // [16,4,64,512]
    const float* bf   = (const float*)d_in[1];  // [16,1,14,64,512]
    const float* mask = (const float*)d_in[2];  // [16,1,64,512]
    float* out = (float*)d_out;

    float* sa = nullptr;
    float* sb = nullptr;
    cudaGetSymbolAddress((void**)&sa, g_scratchA);
    cudaGetSymbolAddress((void**)&sb, g_scratchB);

    dim3 block(TW, TH, 1);                  // 512 threads
    dim3 grid(WW / TW, HH / TH, BATCH);     // 8 x 8 x 16 = 1024 blocks

    crf_iter_kernel<<<grid, block>>>(x,  bf, mask, sa);
    crf_iter_kernel<<<grid, block>>>(sa, bf, mask, sb);
    crf_iter_kernel<<<grid, block>>>(sb, bf, mask, out);
}